// round 7
// baseline (speedup 1.0000x reference)
#include <cuda_runtime.h>
#include <cuda_fp16.h>
#include <math.h>
#include <stdint.h>

#define N_NODES  100000
#define N_HEDGES 100000
#define N_INC    3200000
#define N_LINKS  262144
#define C1 128
#define C2 256

#define SCAN_ELEMS 1024
#define SCAN_BLOCKS ((N_NODES + SCAN_ELEMS - 1) / SCAN_ELEMS)   // 98

#define NCHUNK 4

// ---------------- device scratch (static; no cudaMalloc) ----------------
__device__ int   g_dv_cnt[N_NODES];
__device__ int   g_node_off[N_NODES + 1];
__device__ int   g_edge_off[N_HEDGES + 1];
__device__ int   g_cursor[N_NODES];
__device__ int   g_node_edges[N_INC];
__device__ int   g_blk_sums[SCAN_BLOCKS];
__device__ int   g_blk_offs[SCAN_BLOCKS];
__device__ float g_dvi[N_NODES];    // Dv^{-1/2}
__device__ float g_te[N_HEDGES];
__device__ float g_s[N_NODES];      // s = S*1
__device__ float g_zfc[N_NODES];
__device__ __half g_Xh [(size_t)N_NODES * C1];   // X as fp16
__device__ __half g_X2h[(size_t)N_NODES * C1];   // S*X (fp16, GEMM1 input)
__device__ __half g_hh [(size_t)N_NODES * C2];   // h (fp16, GEMM2 input)
__device__ __half g_th [(size_t)N_NODES * C1];   // h W2 (fp16)
__device__ __half g_W1T[(size_t)C2 * C1];        // W1^T fp16 [256,128]
__device__ __half g_W2T[(size_t)C1 * C2];        // W2^T fp16 [128,256]
__device__ __half g_Yeh[(size_t)N_HEDGES * C1];  // per-edge aggregate scratch fp16

// ---------------- setup kernels ----------------
__global__ __launch_bounds__(256)
void zero_counts_kernel() {
    int i = blockIdx.x * 256 + threadIdx.x;
    if (i < N_NODES) { g_dv_cnt[i] = 0; g_cursor[i] = 0; }
}

__global__ __launch_bounds__(256)
void count_kernel(const int* __restrict__ inc_v) {
    int i = blockIdx.x * 256 + threadIdx.x;
    if (i < N_INC) atomicAdd(&g_dv_cnt[inc_v[i]], 1);
}

__global__ __launch_bounds__(256)
void node_scan_phase1() {
    int b = blockIdx.x, t = threadIdx.x;
    int base = b * SCAN_ELEMS + t * 4;
    int s = 0;
    #pragma unroll
    for (int k = 0; k < 4; k++) { int i = base + k; if (i < N_NODES) s += g_dv_cnt[i]; }
    __shared__ int sh[256];
    sh[t] = s; __syncthreads();
    #pragma unroll
    for (int d = 128; d > 0; d >>= 1) { if (t < d) sh[t] += sh[t + d]; __syncthreads(); }
    if (t == 0) g_blk_sums[b] = sh[0];
}

__global__ __launch_bounds__(128)
void node_scan_phase2() {
    int t = threadIdx.x;
    __shared__ int sh[128];
    int v = (t < SCAN_BLOCKS) ? g_blk_sums[t] : 0;
    sh[t] = v; __syncthreads();
    #pragma unroll
    for (int d = 1; d < 128; d <<= 1) {
        int x = (t >= d) ? sh[t - d] : 0; __syncthreads(); sh[t] += x; __syncthreads();
    }
    if (t < SCAN_BLOCKS) g_blk_offs[t] = sh[t] - v;
    if (t == 127) g_node_off[N_NODES] = sh[127];
}

__global__ __launch_bounds__(256)
void node_scan_phase3() {
    int b = blockIdx.x, t = threadIdx.x;
    int base = b * SCAN_ELEMS + t * 4;
    int c[4]; int s = 0;
    #pragma unroll
    for (int k = 0; k < 4; k++) { int i = base + k; c[k] = (i < N_NODES) ? g_dv_cnt[i] : 0; s += c[k]; }
    __shared__ int sh[256];
    sh[t] = s; __syncthreads();
    #pragma unroll
    for (int d = 1; d < 256; d <<= 1) {
        int x = (t >= d) ? sh[t - d] : 0; __syncthreads(); sh[t] += x; __syncthreads();
    }
    int run = g_blk_offs[b] + sh[t] - s;
    #pragma unroll
    for (int k = 0; k < 4; k++) {
        int i = base + k;
        if (i < N_NODES) {
            g_node_off[i] = run; run += c[k];
            g_dvi[i] = (c[k] > 0) ? rsqrtf((float)c[k]) : 0.0f;
        }
    }
}

__global__ __launch_bounds__(256)
void edge_off_kernel(const int* __restrict__ inc_e) {
    int e = blockIdx.x * 256 + threadIdx.x;
    if (e > N_HEDGES) return;
    int lo = 0, hi = N_INC;
    while (lo < hi) { int mid = (lo + hi) >> 1; if (inc_e[mid] < e) lo = mid + 1; else hi = mid; }
    g_edge_off[e] = lo;
}

__global__ __launch_bounds__(256)
void build_csr_kernel(const int* __restrict__ inc_v, const int* __restrict__ inc_e) {
    int i = blockIdx.x * 256 + threadIdx.x;
    if (i < N_INC) {
        int v = inc_v[i];
        int pos = g_node_off[v] + atomicAdd(&g_cursor[v], 1);
        g_node_edges[pos] = inc_e[i];
    }
}

__global__ __launch_bounds__(256)
void te_kernel(const int* __restrict__ inc_v) {
    int e = blockIdx.x * 256 + threadIdx.x;
    if (e >= N_HEDGES) return;
    int b = g_edge_off[e], en = g_edge_off[e + 1];
    float sum = 0.0f;
    for (int i = b; i < en; i++) sum += g_dvi[inc_v[i]];
    float dei = (en > b) ? 1.0f / (float)(en - b) : 0.0f;
    g_te[e] = dei * sum;
}

__global__ __launch_bounds__(256)
void s_kernel() {
    int v = blockIdx.x * 256 + threadIdx.x;
    if (v >= N_NODES) return;
    int b = g_node_off[v], en = g_node_off[v + 1];
    float sum = 0.0f;
    for (int j = b; j < en; j++) sum += g_te[g_node_edges[j]];
    g_s[v] = g_dvi[v] * sum;
}

// weight transpose + fp16: out[n*K + k] = W[k*N + n]
__global__ __launch_bounds__(256)
void wt_kernel(const float* __restrict__ W, __half* __restrict__ out, int K, int N) {
    int i = blockIdx.x * 256 + threadIdx.x;
    if (i < K * N) {
        int n = i / K, k = i % K;
        out[i] = __float2half(W[k * N + n]);
    }
}

// X fp32 -> fp16
__global__ __launch_bounds__(256)
void x_to_h_kernel(const float* __restrict__ X, __half* __restrict__ Xh) {
    int i = blockIdx.x * 256 + threadIdx.x;          // half2 index
    int n = (N_NODES * C1) >> 1;
    if (i < n) {
        float2 v = *(const float2*)(X + i * 2);
        *((__half2*)Xh + i) = __floats2half2_rn(v.x, v.y);
    }
}

// ---------------- gathers ----------------
__device__ __forceinline__ void accum_row_h8(float* a, const __half* __restrict__ row,
                                             int li, float wu) {
    uint4 x = *(const uint4*)(row + li * 8);
    const __half2* hx = (const __half2*)&x;
    float2 f0 = __half22float2(hx[0]);
    float2 f1 = __half22float2(hx[1]);
    float2 f2 = __half22float2(hx[2]);
    float2 f3 = __half22float2(hx[3]);
    a[0] = fmaf(wu, f0.x, a[0]); a[1] = fmaf(wu, f0.y, a[1]);
    a[2] = fmaf(wu, f1.x, a[2]); a[3] = fmaf(wu, f1.y, a[3]);
    a[4] = fmaf(wu, f2.x, a[4]); a[5] = fmaf(wu, f2.y, a[5]);
    a[6] = fmaf(wu, f3.x, a[6]); a[7] = fmaf(wu, f3.y, a[7]);
}

// Ye[e,:] = (1/deg_e) * sum dvi[u] * Xin[u,:]
// use_cnt=1: weight computed from raw counts (rsqrt), allowing launch before scan.
__global__ __launch_bounds__(256)
void edge_agg_h_kernel(const __half* __restrict__ Xin, const int* __restrict__ inc_v,
                       int use_cnt) {
    int w = (blockIdx.x * 256 + threadIdx.x) >> 5;
    if (w >= N_HEDGES) return;
    int lane = threadIdx.x & 31;
    int half = lane >> 4, li = lane & 15;
    int b = g_edge_off[w], e = g_edge_off[w + 1];
    float a[8] = {0.f, 0.f, 0.f, 0.f, 0.f, 0.f, 0.f, 0.f};

    int i = b + half;
    if (use_cnt) {
        for (; i + 2 < e; i += 4) {
            int u0 = inc_v[i], u1 = inc_v[i + 2];
            int c0 = g_dv_cnt[u0], c1 = g_dv_cnt[u1];
            float w0 = (c0 > 0) ? rsqrtf((float)c0) : 0.0f;
            float w1 = (c1 > 0) ? rsqrtf((float)c1) : 0.0f;
            accum_row_h8(a, Xin + (size_t)u0 * C1, li, w0);
            accum_row_h8(a, Xin + (size_t)u1 * C1, li, w1);
        }
        if (i < e) {
            int u = inc_v[i];
            int c = g_dv_cnt[u];
            accum_row_h8(a, Xin + (size_t)u * C1, li, (c > 0) ? rsqrtf((float)c) : 0.0f);
        }
    } else {
        for (; i + 2 < e; i += 4) {
            int u0 = inc_v[i], u1 = inc_v[i + 2];
            float w0 = g_dvi[u0], w1 = g_dvi[u1];
            accum_row_h8(a, Xin + (size_t)u0 * C1, li, w0);
            accum_row_h8(a, Xin + (size_t)u1 * C1, li, w1);
        }
        if (i < e) {
            int u = inc_v[i];
            accum_row_h8(a, Xin + (size_t)u * C1, li, g_dvi[u]);
        }
    }
    #pragma unroll
    for (int r = 0; r < 8; r++) a[r] += __shfl_down_sync(0xffffffffu, a[r], 16);
    if (half == 0) {
        float d = (e > b) ? 1.0f / (float)(e - b) : 0.0f;
        uint4 o;
        ((__half2*)&o)[0] = __floats2half2_rn(a[0] * d, a[1] * d);
        ((__half2*)&o)[1] = __floats2half2_rn(a[2] * d, a[3] * d);
        ((__half2*)&o)[2] = __floats2half2_rn(a[4] * d, a[5] * d);
        ((__half2*)&o)[3] = __floats2half2_rn(a[6] * d, a[7] * d);
        *(uint4*)(g_Yeh + (size_t)w * C1 + li * 8) = o;
    }
}

// Xout[v,:] = dvi[v] * sum_e Ye[e,:] over node range [vbase, vbase+vcount)
__global__ __launch_bounds__(256)
void node_agg_h_kernel(__half* __restrict__ Xout, int vbase, int vcount) {
    int w = (blockIdx.x * 256 + threadIdx.x) >> 5;
    if (w >= vcount) return;
    int v = vbase + w;
    int lane = threadIdx.x & 31;
    int half = lane >> 4, li = lane & 15;
    int b = g_node_off[v], e = g_node_off[v + 1];
    float a[8] = {0.f, 0.f, 0.f, 0.f, 0.f, 0.f, 0.f, 0.f};

    int j = b + half;
    for (; j + 2 < e; j += 4) {
        int e0 = g_node_edges[j], e1 = g_node_edges[j + 2];
        accum_row_h8(a, g_Yeh + (size_t)e0 * C1, li, 1.0f);
        accum_row_h8(a, g_Yeh + (size_t)e1 * C1, li, 1.0f);
    }
    if (j < e) {
        int ee = g_node_edges[j];
        accum_row_h8(a, g_Yeh + (size_t)ee * C1, li, 1.0f);
    }
    #pragma unroll
    for (int r = 0; r < 8; r++) a[r] += __shfl_down_sync(0xffffffffu, a[r], 16);
    if (half == 0) {
        float d = g_dvi[v];
        uint4 o;
        ((__half2*)&o)[0] = __floats2half2_rn(a[0] * d, a[1] * d);
        ((__half2*)&o)[1] = __floats2half2_rn(a[2] * d, a[3] * d);
        ((__half2*)&o)[2] = __floats2half2_rn(a[4] * d, a[5] * d);
        ((__half2*)&o)[3] = __floats2half2_rn(a[6] * d, a[7] * d);
        *(uint4*)(Xout + (size_t)v * C1 + li * 8) = o;
    }
}

// final: zfc[v] = sum_c relu(dvi[v]*agg_c + s[v]*b2[c]) * fcW[c]
__global__ __launch_bounds__(256)
void node_agg_final_kernel(const float* __restrict__ b2, const float* __restrict__ fcW) {
    int v = (blockIdx.x * 256 + threadIdx.x) >> 5;
    if (v >= N_NODES) return;
    int lane = threadIdx.x & 31;
    int half = lane >> 4, li = lane & 15;
    int b = g_node_off[v], e = g_node_off[v + 1];
    float a[8] = {0.f, 0.f, 0.f, 0.f, 0.f, 0.f, 0.f, 0.f};

    int j = b + half;
    for (; j + 2 < e; j += 4) {
        int e0 = g_node_edges[j], e1 = g_node_edges[j + 2];
        accum_row_h8(a, g_Yeh + (size_t)e0 * C1, li, 1.0f);
        accum_row_h8(a, g_Yeh + (size_t)e1 * C1, li, 1.0f);
    }
    if (j < e) {
        int ee = g_node_edges[j];
        accum_row_h8(a, g_Yeh + (size_t)ee * C1, li, 1.0f);
    }
    #pragma unroll
    for (int r = 0; r < 8; r++) a[r] += __shfl_down_sync(0xffffffffu, a[r], 16);

    float p = 0.0f;
    if (half == 0) {
        float d  = g_dvi[v];
        float sv = g_s[v];
        float4 bb0 = *(const float4*)(b2 + li * 8);
        float4 bb1 = *(const float4*)(b2 + li * 8 + 4);
        float4 fw0 = *(const float4*)(fcW + li * 8);
        float4 fw1 = *(const float4*)(fcW + li * 8 + 4);
        p += fmaxf(fmaf(d, a[0], sv * bb0.x), 0.f) * fw0.x;
        p += fmaxf(fmaf(d, a[1], sv * bb0.y), 0.f) * fw0.y;
        p += fmaxf(fmaf(d, a[2], sv * bb0.z), 0.f) * fw0.z;
        p += fmaxf(fmaf(d, a[3], sv * bb0.w), 0.f) * fw0.w;
        p += fmaxf(fmaf(d, a[4], sv * bb1.x), 0.f) * fw1.x;
        p += fmaxf(fmaf(d, a[5], sv * bb1.y), 0.f) * fw1.y;
        p += fmaxf(fmaf(d, a[6], sv * bb1.z), 0.f) * fw1.z;
        p += fmaxf(fmaf(d, a[7], sv * bb1.w), 0.f) * fw1.w;
    }
    #pragma unroll
    for (int o = 8; o > 0; o >>= 1) p += __shfl_down_sync(0xffffffffu, p, o);
    if (lane == 0) g_zfc[v] = p;
}

// ---------------- mma.sync fp16 GEMM: C[M,N] = A[M,K] @ Bt[N,K]^T ----------------
#define GBK 32
#define GSTRIDE (GBK + 8)

__global__ __launch_bounds__(256)
void gemm_mma_kernel(const __half* __restrict__ A, const __half* __restrict__ Bt,
                     int row_base, int M, int K, int N, int mode,
                     const float* __restrict__ rowscale, const float* __restrict__ bias,
                     __half* __restrict__ outH) {
    __shared__ __half As[128 * GSTRIDE];
    __shared__ __half Bs[128 * GSTRIDE];

    int tid = threadIdx.x;
    int wid = tid >> 5, lane = tid & 31;
    int warp_m = wid >> 2;
    int warp_n = wid & 3;
    int gid = lane >> 2;
    int tig = lane & 3;

    int blockRow = row_base + blockIdx.x * 128;
    int blockCol = blockIdx.y * 128;

    float acc[4][4][4];
    #pragma unroll
    for (int i = 0; i < 4; i++)
        #pragma unroll
        for (int j = 0; j < 4; j++)
            #pragma unroll
            for (int r = 0; r < 4; r++) acc[i][j][r] = 0.f;

    for (int k0 = 0; k0 < K; k0 += GBK) {
        #pragma unroll
        for (int it = 0; it < 2; it++) {
            int id = tid + it * 256;
            int r = id >> 2, c8 = (id & 3) << 3;
            int grow = blockRow + r;
            uint4 v = make_uint4(0u, 0u, 0u, 0u);
            if (grow < M) v = *(const uint4*)(A + (size_t)grow * K + k0 + c8);
            *(uint4*)(As + r * GSTRIDE + c8) = v;
        }
        #pragma unroll
        for (int it = 0; it < 2; it++) {
            int id = tid + it * 256;
            int r = id >> 2, c8 = (id & 3) << 3;
            uint4 v = *(const uint4*)(Bt + (size_t)(blockCol + r) * K + k0 + c8);
            *(uint4*)(Bs + r * GSTRIDE + c8) = v;
        }
        __syncthreads();

        #pragma unroll
        for (int k16 = 0; k16 < GBK; k16 += 16) {
            uint32_t af[4][4];
            #pragma unroll
            for (int mt = 0; mt < 4; mt++) {
                int rbase = warp_m * 64 + mt * 16;
                const __half* p0 = As + (rbase + gid) * GSTRIDE + k16 + tig * 2;
                const __half* p1 = As + (rbase + gid + 8) * GSTRIDE + k16 + tig * 2;
                af[mt][0] = *(const uint32_t*)p0;
                af[mt][1] = *(const uint32_t*)p1;
                af[mt][2] = *(const uint32_t*)(p0 + 8);
                af[mt][3] = *(const uint32_t*)(p1 + 8);
            }
            uint32_t bf[4][2];
            #pragma unroll
            for (int nt = 0; nt < 4; nt++) {
                int nrow = warp_n * 32 + nt * 8 + gid;
                const __half* p = Bs + nrow * GSTRIDE + k16 + tig * 2;
                bf[nt][0] = *(const uint32_t*)p;
                bf[nt][1] = *(const uint32_t*)(p + 8);
            }
            #pragma unroll
            for (int mt = 0; mt < 4; mt++)
                #pragma unroll
                for (int nt = 0; nt < 4; nt++) {
                    asm volatile(
                        "mma.sync.aligned.m16n8k16.row.col.f32.f16.f16.f32 "
                        "{%0,%1,%2,%3}, {%4,%5,%6,%7}, {%8,%9}, {%0,%1,%2,%3};"
                        : "+f"(acc[mt][nt][0]), "+f"(acc[mt][nt][1]),
                          "+f"(acc[mt][nt][2]), "+f"(acc[mt][nt][3])
                        : "r"(af[mt][0]), "r"(af[mt][1]), "r"(af[mt][2]), "r"(af[mt][3]),
                          "r"(bf[nt][0]), "r"(bf[nt][1]));
                }
        }
        __syncthreads();
    }

    #pragma unroll
    for (int mt = 0; mt < 4; mt++) {
        #pragma unroll
        for (int half = 0; half < 2; half++) {
            int row = blockRow + warp_m * 64 + mt * 16 + gid + half * 8;
            if (row >= M) continue;
            float rs = (mode == 1) ? rowscale[row] : 0.f;
            #pragma unroll
            for (int nt = 0; nt < 4; nt++) {
                int col = blockCol + warp_n * 32 + nt * 8 + tig * 2;
                float v0 = acc[mt][nt][half * 2 + 0];
                float v1 = acc[mt][nt][half * 2 + 1];
                if (mode == 1) {
                    v0 = fmaxf(fmaf(rs, bias[col],     v0), 0.f);
                    v1 = fmaxf(fmaf(rs, bias[col + 1], v1), 0.f);
                }
                *(__half2*)(outH + (size_t)row * N + col) = __floats2half2_rn(v0, v1);
            }
        }
    }
}

// ---------------- link scoring ----------------
__global__ __launch_bounds__(256)
void link_kernel(const int* __restrict__ link, const float* __restrict__ fcb,
                 float* __restrict__ out) {
    int i = blockIdx.x * 256 + threadIdx.x;
    if (i >= N_LINKS) return;
    int a = link[2 * i], b = link[2 * i + 1];
    float x = (g_zfc[a] + g_zfc[b]) * 0.5f + fcb[0];
    out[i] = 1.0f / (1.0f + __expf(-x));
}

// ---------------- launch ----------------
extern "C" void kernel_launch(void* const* d_in, const int* in_sizes, int n_in,
                              void* d_out, int out_size) {
    const float* X    = (const float*)d_in[0];
    const float* W1   = (const float*)d_in[1];
    const float* b1   = (const float*)d_in[2];
    const float* W2   = (const float*)d_in[3];
    const float* b2   = (const float*)d_in[4];
    const float* fcW  = (const float*)d_in[5];
    const float* fcb  = (const float*)d_in[6];
    const int*   incv = (const int*)d_in[7];
    const int*   ince = (const int*)d_in[8];
    const int*   link = (const int*)d_in[9];
    float* out = (float*)d_out;

    static float*  p_s   = nullptr;
    static __half* p_Xh  = nullptr;
    static __half* p_X2h = nullptr;
    static __half* p_hh  = nullptr;
    static __half* p_th  = nullptr;
    static __half* p_W1T = nullptr;
    static __half* p_W2T = nullptr;
    static cudaStream_t s2 = nullptr, s3 = nullptr, s4 = nullptr;
    static cudaEvent_t evFork = nullptr, evB = nullptr, evCount = nullptr,
                       evCsr = nullptr, evS = nullptr, evGemm = nullptr;
    static cudaEvent_t evNA[NCHUNK] = {};
    if (!p_s) {
        cudaGetSymbolAddress((void**)&p_s,   g_s);
        cudaGetSymbolAddress((void**)&p_Xh,  g_Xh);
        cudaGetSymbolAddress((void**)&p_X2h, g_X2h);
        cudaGetSymbolAddress((void**)&p_hh,  g_hh);
        cudaGetSymbolAddress((void**)&p_th,  g_th);
        cudaGetSymbolAddress((void**)&p_W1T, g_W1T);
        cudaGetSymbolAddress((void**)&p_W2T, g_W2T);
        cudaStreamCreateWithFlags(&s2, cudaStreamNonBlocking);
        cudaStreamCreateWithFlags(&s3, cudaStreamNonBlocking);
        cudaStreamCreateWithFlags(&s4, cudaStreamNonBlocking);
        cudaEventCreateWithFlags(&evFork,  cudaEventDisableTiming);
        cudaEventCreateWithFlags(&evB,     cudaEventDisableTiming);
        cudaEventCreateWithFlags(&evCount, cudaEventDisableTiming);
        cudaEventCreateWithFlags(&evCsr,   cudaEventDisableTiming);
        cudaEventCreateWithFlags(&evS,     cudaEventDisableTiming);
        cudaEventCreateWithFlags(&evGemm,  cudaEventDisableTiming);
        for (int c = 0; c < NCHUNK; c++)
            cudaEventCreateWithFlags(&evNA[c], cudaEventDisableTiming);
    }

    const int TPB = 256;
    int inc_blocks    = (N_INC + TPB - 1) / TPB;
    int node_blocks   = (N_NODES + TPB - 1) / TPB;
    int edge_blocks   = (N_HEDGES + 1 + TPB - 1) / TPB;
    int warp_blocks_e = (N_HEDGES * 32 + TPB - 1) / TPB;
    int warp_blocks_n = (N_NODES * 32 + TPB - 1) / TPB;
    int wt_blocks     = (C1 * C2 + TPB - 1) / TPB;
    int xh_blocks     = ((N_NODES * C1 / 2) + TPB - 1) / TPB;

    // chunk layout aligned to 128-row GEMM blocks: 196+196+196+194 = 782
    const int chunk_blocks[NCHUNK] = {196, 196, 196, 194};
    const int chunk_base[NCHUNK]   = {0, 25088, 50176, 75264};
    const int chunk_rows[NCHUNK]   = {25088, 25088, 25088, N_NODES - 75264};

    // ---- branch B (s2): edge_off, Xh, weight transposes ----
    cudaEventRecord(evFork, 0);
    cudaStreamWaitEvent(s2, evFork, 0);
    edge_off_kernel<<<edge_blocks, TPB, 0, s2>>>(ince);
    x_to_h_kernel<<<xh_blocks, TPB, 0, s2>>>(X, p_Xh);
    wt_kernel<<<wt_blocks, TPB, 0, s2>>>(W1, p_W1T, C1, C2);
    wt_kernel<<<wt_blocks, TPB, 0, s2>>>(W2, p_W2T, C2, C1);
    cudaEventRecord(evB, s2);

    // ---- main: counts only, then edge_agg1 (uses raw counts for dvi) ----
    zero_counts_kernel<<<node_blocks, TPB>>>();
    count_kernel<<<inc_blocks, TPB>>>(incv);
    cudaEventRecord(evCount, 0);

    // ---- branch C (s3): scan + csr + te + s, overlapped with edge_agg1 ----
    cudaStreamWaitEvent(s3, evCount, 0);
    cudaStreamWaitEvent(s3, evB, 0);
    node_scan_phase1<<<SCAN_BLOCKS, TPB, 0, s3>>>();
    node_scan_phase2<<<1, 128, 0, s3>>>();
    node_scan_phase3<<<SCAN_BLOCKS, TPB, 0, s3>>>();
    build_csr_kernel<<<inc_blocks, TPB, 0, s3>>>(incv, ince);
    cudaEventRecord(evCsr, s3);
    te_kernel<<<node_blocks, TPB, 0, s3>>>(incv);
    s_kernel<<<node_blocks, TPB, 0, s3>>>();
    cudaEventRecord(evS, s3);

    // ---- main: edge aggregation layer 1 ----
    cudaStreamWaitEvent(0, evB, 0);
    edge_agg_h_kernel<<<warp_blocks_e, TPB>>>(p_Xh, incv, /*use_cnt=*/1);

    // ---- chunked pipeline: node_agg (main) || GEMM1+GEMM2 (s4) ----
    cudaStreamWaitEvent(0, evCsr, 0);
    cudaStreamWaitEvent(s4, evS, 0);
    for (int c = 0; c < NCHUNK; c++) {
        int nb = (chunk_rows[c] * 32 + TPB - 1) / TPB;
        node_agg_h_kernel<<<nb, TPB>>>(p_X2h, chunk_base[c], chunk_rows[c]);
        cudaEventRecord(evNA[c], 0);
        cudaStreamWaitEvent(s4, evNA[c], 0);
        dim3 g1(chunk_blocks[c], C2 / 128);
        gemm_mma_kernel<<<g1, 256, 0, s4>>>(p_X2h, p_W1T, chunk_base[c], N_NODES,
                                            C1, C2, 1, p_s, b1, p_hh);
        dim3 g2(chunk_blocks[c], C1 / 128);
        gemm_mma_kernel<<<g2, 256, 0, s4>>>(p_hh, p_W2T, chunk_base[c], N_NODES,
                                            C2, C1, 0, nullptr, nullptr, p_th);
    }
    cudaEventRecord(evGemm, s4);

    // ---- layer 2 smoothing + output ----
    cudaStreamWaitEvent(0, evGemm, 0);
    edge_agg_h_kernel<<<warp_blocks_e, TPB>>>(p_th, incv, /*use_cnt=*/0);
    node_agg_final_kernel<<<warp_blocks_n, TPB>>>(b2, fcW);
    link_kernel<<<(N_LINKS + TPB - 1) / TPB, TPB>>>(link, fcb, out);
    (void)in_sizes; (void)n_in; (void)out_size;
}

// round 8
// speedup vs baseline: 1.1080x; 1.1080x over previous
#include <cuda_runtime.h>
#include <cuda_fp16.h>
#include <math.h>
#include <stdint.h>

#define N_NODES  100000
#define N_HEDGES 100000
#define N_INC    3200000
#define N_LINKS  262144
#define C1 128
#define C2 256

#define SCAN_ELEMS 1024
#define SCAN_BLOCKS ((N_NODES + SCAN_ELEMS - 1) / SCAN_ELEMS)   // 98

// ---------------- device scratch (static; no cudaMalloc) ----------------
__device__ int   g_dv_cnt[N_NODES];
__device__ int   g_node_off[N_NODES + 1];
__device__ int   g_edge_off[N_HEDGES + 1];
__device__ int   g_cursor[N_NODES];
__device__ int   g_node_edges[N_INC];
__device__ int   g_blk_sums[SCAN_BLOCKS];
__device__ int   g_blk_offs[SCAN_BLOCKS];
__device__ float g_dvi[N_NODES];    // Dv^{-1/2}
__device__ float g_te[N_HEDGES];
__device__ float g_s[N_NODES];      // s = S*1
__device__ float g_zfc[N_NODES];
__device__ __half g_Xh [(size_t)N_NODES * C1];   // X as fp16
__device__ __half g_X2h[(size_t)N_NODES * C1];   // S*X (fp16, GEMM1 input)
__device__ __half g_hh [(size_t)N_NODES * C2];   // h (fp16, GEMM2 input)
__device__ __half g_th [(size_t)N_NODES * C1];   // h W2 (fp16)
__device__ __half g_W1T[(size_t)C2 * C1];        // W1^T fp16 [256,128]
__device__ __half g_W2T[(size_t)C1 * C2];        // W2^T fp16 [128,256]
__device__ __half g_Yeh[(size_t)N_HEDGES * C1];  // per-edge aggregate scratch fp16

// ---------------- cp.async helpers ----------------
__device__ __forceinline__ void cp_async16(void* dst, const void* src, bool pred) {
    uint32_t d = (uint32_t)__cvta_generic_to_shared(dst);
    int sz = pred ? 16 : 0;
    asm volatile("cp.async.cg.shared.global [%0], [%1], 16, %2;"
                 :: "r"(d), "l"(src), "r"(sz));
}
#define CP_COMMIT()  asm volatile("cp.async.commit_group;" ::: "memory")
#define CP_WAIT_1()  asm volatile("cp.async.wait_group 1;" ::: "memory")
#define CP_WAIT_0()  asm volatile("cp.async.wait_group 0;" ::: "memory")

// ---------------- setup kernels ----------------
__global__ __launch_bounds__(256)
void zero_counts_kernel() {
    int i = blockIdx.x * 256 + threadIdx.x;
    if (i < N_NODES) { g_dv_cnt[i] = 0; g_cursor[i] = 0; }
}

__global__ __launch_bounds__(256)
void count_kernel(const int* __restrict__ inc_v) {
    int i = blockIdx.x * 256 + threadIdx.x;
    if (i < N_INC) atomicAdd(&g_dv_cnt[inc_v[i]], 1);
}

__global__ __launch_bounds__(256)
void node_scan_phase1() {
    int b = blockIdx.x, t = threadIdx.x;
    int base = b * SCAN_ELEMS + t * 4;
    int s = 0;
    #pragma unroll
    for (int k = 0; k < 4; k++) { int i = base + k; if (i < N_NODES) s += g_dv_cnt[i]; }
    __shared__ int sh[256];
    sh[t] = s; __syncthreads();
    #pragma unroll
    for (int d = 128; d > 0; d >>= 1) { if (t < d) sh[t] += sh[t + d]; __syncthreads(); }
    if (t == 0) g_blk_sums[b] = sh[0];
}

__global__ __launch_bounds__(128)
void node_scan_phase2() {
    int t = threadIdx.x;
    __shared__ int sh[128];
    int v = (t < SCAN_BLOCKS) ? g_blk_sums[t] : 0;
    sh[t] = v; __syncthreads();
    #pragma unroll
    for (int d = 1; d < 128; d <<= 1) {
        int x = (t >= d) ? sh[t - d] : 0; __syncthreads(); sh[t] += x; __syncthreads();
    }
    if (t < SCAN_BLOCKS) g_blk_offs[t] = sh[t] - v;
    if (t == 127) g_node_off[N_NODES] = sh[127];
}

__global__ __launch_bounds__(256)
void node_scan_phase3() {
    int b = blockIdx.x, t = threadIdx.x;
    int base = b * SCAN_ELEMS + t * 4;
    int c[4]; int s = 0;
    #pragma unroll
    for (int k = 0; k < 4; k++) { int i = base + k; c[k] = (i < N_NODES) ? g_dv_cnt[i] : 0; s += c[k]; }
    __shared__ int sh[256];
    sh[t] = s; __syncthreads();
    #pragma unroll
    for (int d = 1; d < 256; d <<= 1) {
        int x = (t >= d) ? sh[t - d] : 0; __syncthreads(); sh[t] += x; __syncthreads();
    }
    int run = g_blk_offs[b] + sh[t] - s;
    #pragma unroll
    for (int k = 0; k < 4; k++) {
        int i = base + k;
        if (i < N_NODES) {
            g_node_off[i] = run; run += c[k];
            g_dvi[i] = (c[k] > 0) ? rsqrtf((float)c[k]) : 0.0f;
        }
    }
}

__global__ __launch_bounds__(256)
void edge_off_kernel(const int* __restrict__ inc_e) {
    int e = blockIdx.x * 256 + threadIdx.x;
    if (e > N_HEDGES) return;
    int lo = 0, hi = N_INC;
    while (lo < hi) { int mid = (lo + hi) >> 1; if (inc_e[mid] < e) lo = mid + 1; else hi = mid; }
    g_edge_off[e] = lo;
}

__global__ __launch_bounds__(256)
void build_csr_kernel(const int* __restrict__ inc_v, const int* __restrict__ inc_e) {
    int i = blockIdx.x * 256 + threadIdx.x;
    if (i < N_INC) {
        int v = inc_v[i];
        int pos = g_node_off[v] + atomicAdd(&g_cursor[v], 1);
        g_node_edges[pos] = inc_e[i];
    }
}

__global__ __launch_bounds__(256)
void te_kernel(const int* __restrict__ inc_v) {
    int e = blockIdx.x * 256 + threadIdx.x;
    if (e >= N_HEDGES) return;
    int b = g_edge_off[e], en = g_edge_off[e + 1];
    float sum = 0.0f;
    for (int i = b; i < en; i++) sum += g_dvi[inc_v[i]];
    float dei = (en > b) ? 1.0f / (float)(en - b) : 0.0f;
    g_te[e] = dei * sum;
}

__global__ __launch_bounds__(256)
void s_kernel() {
    int v = blockIdx.x * 256 + threadIdx.x;
    if (v >= N_NODES) return;
    int b = g_node_off[v], en = g_node_off[v + 1];
    float sum = 0.0f;
    for (int j = b; j < en; j++) sum += g_te[g_node_edges[j]];
    g_s[v] = g_dvi[v] * sum;
}

// weight transpose + fp16: out[n*K + k] = W[k*N + n]
__global__ __launch_bounds__(256)
void wt_kernel(const float* __restrict__ W, __half* __restrict__ out, int K, int N) {
    int i = blockIdx.x * 256 + threadIdx.x;
    if (i < K * N) {
        int n = i / K, k = i % K;
        out[i] = __float2half(W[k * N + n]);
    }
}

// X fp32 -> fp16
__global__ __launch_bounds__(256)
void x_to_h_kernel(const float* __restrict__ X, __half* __restrict__ Xh) {
    int i = blockIdx.x * 256 + threadIdx.x;
    int n = (N_NODES * C1) >> 1;
    if (i < n) {
        float2 v = *(const float2*)(X + i * 2);
        *((__half2*)Xh + i) = __floats2half2_rn(v.x, v.y);
    }
}

// ---------------- gathers ----------------
__device__ __forceinline__ void accum_row_h8(float* a, const __half* __restrict__ row,
                                             int li, float wu) {
    uint4 x = *(const uint4*)(row + li * 8);
    const __half2* hx = (const __half2*)&x;
    float2 f0 = __half22float2(hx[0]);
    float2 f1 = __half22float2(hx[1]);
    float2 f2 = __half22float2(hx[2]);
    float2 f3 = __half22float2(hx[3]);
    a[0] = fmaf(wu, f0.x, a[0]); a[1] = fmaf(wu, f0.y, a[1]);
    a[2] = fmaf(wu, f1.x, a[2]); a[3] = fmaf(wu, f1.y, a[3]);
    a[4] = fmaf(wu, f2.x, a[4]); a[5] = fmaf(wu, f2.y, a[5]);
    a[6] = fmaf(wu, f3.x, a[6]); a[7] = fmaf(wu, f3.y, a[7]);
}

// Ye[e,:] = (1/deg_e) * sum dvi[u] * Xin[u,:]
__global__ __launch_bounds__(256)
void edge_agg_h_kernel(const __half* __restrict__ Xin, const int* __restrict__ inc_v) {
    int w = (blockIdx.x * 256 + threadIdx.x) >> 5;
    if (w >= N_HEDGES) return;
    int lane = threadIdx.x & 31;
    int half = lane >> 4, li = lane & 15;
    int b = g_edge_off[w], e = g_edge_off[w + 1];
    float a[8] = {0.f, 0.f, 0.f, 0.f, 0.f, 0.f, 0.f, 0.f};

    int i = b + half;
    for (; i + 2 < e; i += 4) {
        int u0 = inc_v[i], u1 = inc_v[i + 2];
        float w0 = g_dvi[u0], w1 = g_dvi[u1];
        accum_row_h8(a, Xin + (size_t)u0 * C1, li, w0);
        accum_row_h8(a, Xin + (size_t)u1 * C1, li, w1);
    }
    if (i < e) {
        int u = inc_v[i];
        accum_row_h8(a, Xin + (size_t)u * C1, li, g_dvi[u]);
    }
    #pragma unroll
    for (int r = 0; r < 8; r++) a[r] += __shfl_down_sync(0xffffffffu, a[r], 16);
    if (half == 0) {
        float d = (e > b) ? 1.0f / (float)(e - b) : 0.0f;
        uint4 o;
        ((__half2*)&o)[0] = __floats2half2_rn(a[0] * d, a[1] * d);
        ((__half2*)&o)[1] = __floats2half2_rn(a[2] * d, a[3] * d);
        ((__half2*)&o)[2] = __floats2half2_rn(a[4] * d, a[5] * d);
        ((__half2*)&o)[3] = __floats2half2_rn(a[6] * d, a[7] * d);
        *(uint4*)(g_Yeh + (size_t)w * C1 + li * 8) = o;
    }
}

// Xout[v,:] = dvi[v] * sum_e Ye[e,:]
__global__ __launch_bounds__(256)
void node_agg_h_kernel(__half* __restrict__ Xout) {
    int v = (blockIdx.x * 256 + threadIdx.x) >> 5;
    if (v >= N_NODES) return;
    int lane = threadIdx.x & 31;
    int half = lane >> 4, li = lane & 15;
    int b = g_node_off[v], e = g_node_off[v + 1];
    float a[8] = {0.f, 0.f, 0.f, 0.f, 0.f, 0.f, 0.f, 0.f};

    int j = b + half;
    for (; j + 2 < e; j += 4) {
        int e0 = g_node_edges[j], e1 = g_node_edges[j + 2];
        accum_row_h8(a, g_Yeh + (size_t)e0 * C1, li, 1.0f);
        accum_row_h8(a, g_Yeh + (size_t)e1 * C1, li, 1.0f);
    }
    if (j < e) {
        int ee = g_node_edges[j];
        accum_row_h8(a, g_Yeh + (size_t)ee * C1, li, 1.0f);
    }
    #pragma unroll
    for (int r = 0; r < 8; r++) a[r] += __shfl_down_sync(0xffffffffu, a[r], 16);
    if (half == 0) {
        float d = g_dvi[v];
        uint4 o;
        ((__half2*)&o)[0] = __floats2half2_rn(a[0] * d, a[1] * d);
        ((__half2*)&o)[1] = __floats2half2_rn(a[2] * d, a[3] * d);
        ((__half2*)&o)[2] = __floats2half2_rn(a[4] * d, a[5] * d);
        ((__half2*)&o)[3] = __floats2half2_rn(a[6] * d, a[7] * d);
        *(uint4*)(Xout + (size_t)v * C1 + li * 8) = o;
    }
}

// final: zfc[v] = sum_c relu(dvi[v]*agg_c + s[v]*b2[c]) * fcW[c]
__global__ __launch_bounds__(256)
void node_agg_final_kernel(const float* __restrict__ b2, const float* __restrict__ fcW) {
    int v = (blockIdx.x * 256 + threadIdx.x) >> 5;
    if (v >= N_NODES) return;
    int lane = threadIdx.x & 31;
    int half = lane >> 4, li = lane & 15;
    int b = g_node_off[v], e = g_node_off[v + 1];
    float a[8] = {0.f, 0.f, 0.f, 0.f, 0.f, 0.f, 0.f, 0.f};

    int j = b + half;
    for (; j + 2 < e; j += 4) {
        int e0 = g_node_edges[j], e1 = g_node_edges[j + 2];
        accum_row_h8(a, g_Yeh + (size_t)e0 * C1, li, 1.0f);
        accum_row_h8(a, g_Yeh + (size_t)e1 * C1, li, 1.0f);
    }
    if (j < e) {
        int ee = g_node_edges[j];
        accum_row_h8(a, g_Yeh + (size_t)ee * C1, li, 1.0f);
    }
    #pragma unroll
    for (int r = 0; r < 8; r++) a[r] += __shfl_down_sync(0xffffffffu, a[r], 16);

    float p = 0.0f;
    if (half == 0) {
        float d  = g_dvi[v];
        float sv = g_s[v];
        float4 bb0 = *(const float4*)(b2 + li * 8);
        float4 bb1 = *(const float4*)(b2 + li * 8 + 4);
        float4 fw0 = *(const float4*)(fcW + li * 8);
        float4 fw1 = *(const float4*)(fcW + li * 8 + 4);
        p += fmaxf(fmaf(d, a[0], sv * bb0.x), 0.f) * fw0.x;
        p += fmaxf(fmaf(d, a[1], sv * bb0.y), 0.f) * fw0.y;
        p += fmaxf(fmaf(d, a[2], sv * bb0.z), 0.f) * fw0.z;
        p += fmaxf(fmaf(d, a[3], sv * bb0.w), 0.f) * fw0.w;
        p += fmaxf(fmaf(d, a[4], sv * bb1.x), 0.f) * fw1.x;
        p += fmaxf(fmaf(d, a[5], sv * bb1.y), 0.f) * fw1.y;
        p += fmaxf(fmaf(d, a[6], sv * bb1.z), 0.f) * fw1.z;
        p += fmaxf(fmaf(d, a[7], sv * bb1.w), 0.f) * fw1.w;
    }
    #pragma unroll
    for (int o = 8; o > 0; o >>= 1) p += __shfl_down_sync(0xffffffffu, p, o);
    if (lane == 0) g_zfc[v] = p;
}

// ---------------- mma.sync fp16 GEMM with cp.async double buffering ----------------
#define GBK 32
#define GSTRIDE (GBK + 8)

__global__ __launch_bounds__(256)
void gemm_mma_kernel(const __half* __restrict__ A, const __half* __restrict__ Bt,
                     int M, int K, int N, int mode,
                     const float* __restrict__ rowscale, const float* __restrict__ bias,
                     __half* __restrict__ outH) {
    __shared__ __half As[2][128 * GSTRIDE];
    __shared__ __half Bs[2][128 * GSTRIDE];

    int tid = threadIdx.x;
    int wid = tid >> 5, lane = tid & 31;
    int warp_m = wid >> 2;
    int warp_n = wid & 3;
    int gid = lane >> 2;
    int tig = lane & 3;

    int blockRow = blockIdx.x * 128;
    int blockCol = blockIdx.y * 128;

    // per-thread tile-load coordinates (2 iters x 16B)
    int lr0 = tid >> 2, lc0 = (tid & 3) << 3;          // rows 0..63
    int lr1 = lr0 + 64;                                 // rows 64..127

    auto issue_tile = [&](int k0, int buf) {
        // A rows: guard M
        {
            int grow = blockRow + lr0;
            bool p = grow < M;
            cp_async16(&As[buf][lr0 * GSTRIDE + lc0],
                       A + (size_t)(p ? grow : 0) * K + k0 + lc0, p);
            grow = blockRow + lr1;
            p = grow < M;
            cp_async16(&As[buf][lr1 * GSTRIDE + lc0],
                       A + (size_t)(p ? grow : 0) * K + k0 + lc0, p);
        }
        // B rows: always in-bounds (N multiple of 128)
        cp_async16(&Bs[buf][lr0 * GSTRIDE + lc0],
                   Bt + (size_t)(blockCol + lr0) * K + k0 + lc0, true);
        cp_async16(&Bs[buf][lr1 * GSTRIDE + lc0],
                   Bt + (size_t)(blockCol + lr1) * K + k0 + lc0, true);
        CP_COMMIT();
    };

    float acc[4][4][4];
    #pragma unroll
    for (int i = 0; i < 4; i++)
        #pragma unroll
        for (int j = 0; j < 4; j++)
            #pragma unroll
            for (int r = 0; r < 4; r++) acc[i][j][r] = 0.f;

    issue_tile(0, 0);
    int buf = 0;
    for (int k0 = 0; k0 < K; k0 += GBK, buf ^= 1) {
        bool more = (k0 + GBK) < K;
        if (more) issue_tile(k0 + GBK, buf ^ 1);
        if (more) { CP_WAIT_1(); } else { CP_WAIT_0(); }
        __syncthreads();

        #pragma unroll
        for (int k16 = 0; k16 < GBK; k16 += 16) {
            uint32_t af[4][4];
            #pragma unroll
            for (int mt = 0; mt < 4; mt++) {
                int rbase = warp_m * 64 + mt * 16;
                const __half* p0 = &As[buf][(rbase + gid) * GSTRIDE + k16 + tig * 2];
                const __half* p1 = &As[buf][(rbase + gid + 8) * GSTRIDE + k16 + tig * 2];
                af[mt][0] = *(const uint32_t*)p0;
                af[mt][1] = *(const uint32_t*)p1;
                af[mt][2] = *(const uint32_t*)(p0 + 8);
                af[mt][3] = *(const uint32_t*)(p1 + 8);
            }
            uint32_t bf[4][2];
            #pragma unroll
            for (int nt = 0; nt < 4; nt++) {
                int nrow = warp_n * 32 + nt * 8 + gid;
                const __half* p = &Bs[buf][nrow * GSTRIDE + k16 + tig * 2];
                bf[nt][0] = *(const uint32_t*)p;
                bf[nt][1] = *(const uint32_t*)(p + 8);
            }
            #pragma unroll
            for (int mt = 0; mt < 4; mt++)
                #pragma unroll
                for (int nt = 0; nt < 4; nt++) {
                    asm volatile(
                        "mma.sync.aligned.m16n8k16.row.col.f32.f16.f16.f32 "
                        "{%0,%1,%2,%3}, {%4,%5,%6,%7}, {%8,%9}, {%0,%1,%2,%3};"
                        : "+f"(acc[mt][nt][0]), "+f"(acc[mt][nt][1]),
                          "+f"(acc[mt][nt][2]), "+f"(acc[mt][nt][3])
                        : "r"(af[mt][0]), "r"(af[mt][1]), "r"(af[mt][2]), "r"(af[mt][3]),
                          "r"(bf[nt][0]), "r"(bf[nt][1]));
                }
        }
        __syncthreads();
    }

    #pragma unroll
    for (int mt = 0; mt < 4; mt++) {
        #pragma unroll
        for (int half = 0; half < 2; half++) {
            int row = blockRow + warp_m * 64 + mt * 16 + gid + half * 8;
            if (row >= M) continue;
            float rs = (mode == 1) ? rowscale[row] : 0.f;
            #pragma unroll
            for (int nt = 0; nt < 4; nt++) {
                int col = blockCol + warp_n * 32 + nt * 8 + tig * 2;
                float v0 = acc[mt][nt][half * 2 + 0];
                float v1 = acc[mt][nt][half * 2 + 1];
                if (mode == 1) {
                    v0 = fmaxf(fmaf(rs, bias[col],     v0), 0.f);
                    v1 = fmaxf(fmaf(rs, bias[col + 1], v1), 0.f);
                }
                *(__half2*)(outH + (size_t)row * N + col) = __floats2half2_rn(v0, v1);
            }
        }
    }
}

// ---------------- link scoring ----------------
__global__ __launch_bounds__(256)
void link_kernel(const int* __restrict__ link, const float* __restrict__ fcb,
                 float* __restrict__ out) {
    int i = blockIdx.x * 256 + threadIdx.x;
    if (i >= N_LINKS) return;
    int a = link[2 * i], b = link[2 * i + 1];
    float x = (g_zfc[a] + g_zfc[b]) * 0.5f + fcb[0];
    out[i] = 1.0f / (1.0f + __expf(-x));
}

// ---------------- launch (R6 structure) ----------------
extern "C" void kernel_launch(void* const* d_in, const int* in_sizes, int n_in,
                              void* d_out, int out_size) {
    const float* X    = (const float*)d_in[0];
    const float* W1   = (const float*)d_in[1];
    const float* b1   = (const float*)d_in[2];
    const float* W2   = (const float*)d_in[3];
    const float* b2   = (const float*)d_in[4];
    const float* fcW  = (const float*)d_in[5];
    const float* fcb  = (const float*)d_in[6];
    const int*   incv = (const int*)d_in[7];
    const int*   ince = (const int*)d_in[8];
    const int*   link = (const int*)d_in[9];
    float* out = (float*)d_out;

    static float*  p_s   = nullptr;
    static __half* p_Xh  = nullptr;
    static __half* p_X2h = nullptr;
    static __half* p_hh  = nullptr;
    static __half* p_th  = nullptr;
    static __half* p_W1T = nullptr;
    static __half* p_W2T = nullptr;
    static cudaStream_t s2 = nullptr, s3 = nullptr;
    static cudaEvent_t evFork = nullptr, evB = nullptr, evScan = nullptr, evC = nullptr;
    if (!p_s) {
        cudaGetSymbolAddress((void**)&p_s,   g_s);
        cudaGetSymbolAddress((void**)&p_Xh,  g_Xh);
        cudaGetSymbolAddress((void**)&p_X2h, g_X2h);
        cudaGetSymbolAddress((void**)&p_hh,  g_hh);
        cudaGetSymbolAddress((void**)&p_th,  g_th);
        cudaGetSymbolAddress((void**)&p_W1T, g_W1T);
        cudaGetSymbolAddress((void**)&p_W2T, g_W2T);
        cudaStreamCreateWithFlags(&s2, cudaStreamNonBlocking);
        cudaStreamCreateWithFlags(&s3, cudaStreamNonBlocking);
        cudaEventCreateWithFlags(&evFork, cudaEventDisableTiming);
        cudaEventCreateWithFlags(&evB,    cudaEventDisableTiming);
        cudaEventCreateWithFlags(&evScan, cudaEventDisableTiming);
        cudaEventCreateWithFlags(&evC,    cudaEventDisableTiming);
    }

    const int TPB = 256;
    int inc_blocks    = (N_INC + TPB - 1) / TPB;
    int node_blocks   = (N_NODES + TPB - 1) / TPB;
    int edge_blocks   = (N_HEDGES + 1 + TPB - 1) / TPB;
    int warp_blocks_e = (N_HEDGES * 32 + TPB - 1) / TPB;
    int warp_blocks_n = (N_NODES * 32 + TPB - 1) / TPB;
    int wt_blocks     = (C1 * C2 + TPB - 1) / TPB;
    int xh_blocks     = ((N_NODES * C1 / 2) + TPB - 1) / TPB;
    int gemm_rows     = (N_NODES + 127) / 128;   // 782

    // ---- branch B (s2): edge_off, Xh, weight transposes ----
    cudaEventRecord(evFork, 0);
    cudaStreamWaitEvent(s2, evFork, 0);
    edge_off_kernel<<<edge_blocks, TPB, 0, s2>>>(ince);
    x_to_h_kernel<<<xh_blocks, TPB, 0, s2>>>(X, p_Xh);
    wt_kernel<<<wt_blocks, TPB, 0, s2>>>(W1, p_W1T, C1, C2);
    wt_kernel<<<wt_blocks, TPB, 0, s2>>>(W2, p_W2T, C2, C1);
    cudaEventRecord(evB, s2);

    // ---- main: node degrees + offsets ----
    zero_counts_kernel<<<node_blocks, TPB>>>();
    count_kernel<<<inc_blocks, TPB>>>(incv);
    node_scan_phase1<<<SCAN_BLOCKS, TPB>>>();
    node_scan_phase2<<<1, 128>>>();
    node_scan_phase3<<<SCAN_BLOCKS, TPB>>>();
    cudaEventRecord(evScan, 0);

    // ---- branch C (s3): CSR + te + s, overlapped with edge_agg1 on main ----
    cudaStreamWaitEvent(s3, evScan, 0);
    cudaStreamWaitEvent(s3, evB, 0);
    build_csr_kernel<<<inc_blocks, TPB, 0, s3>>>(incv, ince);
    te_kernel<<<node_blocks, TPB, 0, s3>>>(incv);
    s_kernel<<<node_blocks, TPB, 0, s3>>>();
    cudaEventRecord(evC, s3);

    // ---- main: edge aggregation layer 1 ----
    cudaStreamWaitEvent(0, evB, 0);
    edge_agg_h_kernel<<<warp_blocks_e, TPB>>>(p_Xh, incv);

    // ---- join branch C, then node agg + GEMMs + layer 2 ----
    cudaStreamWaitEvent(0, evC, 0);
    node_agg_h_kernel<<<warp_blocks_n, TPB>>>(p_X2h);
    {
        dim3 grid(gemm_rows, C2 / 128);
        gemm_mma_kernel<<<grid, 256>>>(p_X2h, p_W1T, N_NODES, C1, C2, 1, p_s, b1, p_hh);
    }
    {
        dim3 grid(gemm_rows, C1 / 128);
        gemm_mma_kernel<<<grid, 256>>>(p_hh, p_W2T, N_NODES, C2, C1, 0, nullptr, nullptr, p_th);
    }
    edge_agg_h_kernel<<<warp_blocks_e, TPB>>>(p_th, incv);
    node_agg_final_kernel<<<warp_blocks_n, TPB>>>(b2, fcW);
    link_kernel<<<(N_LINKS + TPB - 1) / TPB, TPB>>>(link, fcb, out);
    (void)in_sizes; (void)n_in; (void)out_size;
}

// round 9
// speedup vs baseline: 1.1281x; 1.0181x over previous
#include <cuda_runtime.h>
#include <cuda_fp16.h>
#include <math.h>
#include <stdint.h>

#define N_NODES  100000
#define N_HEDGES 100000
#define N_INC    3200000
#define N_LINKS  262144
#define C1 128
#define C2 256

#define SCAN_ELEMS 1024
#define SCAN_BLOCKS ((N_NODES + SCAN_ELEMS - 1) / SCAN_ELEMS)   // 98

// ---------------- device scratch (static; no cudaMalloc) ----------------
__device__ int   g_dv_cnt[N_NODES];
__device__ int   g_node_off[N_NODES + 1];
__device__ int   g_edge_off[N_HEDGES + 1];
__device__ int   g_cursor[N_NODES];
__device__ int   g_node_edges[N_INC];
__device__ int   g_blk_sums[SCAN_BLOCKS];
__device__ int   g_blk_offs[SCAN_BLOCKS];
__device__ float g_dvi[N_NODES];    // Dv^{-1/2}
__device__ float g_te[N_HEDGES];
__device__ float g_s[N_NODES];      // s = S*1
__device__ float g_zfc[N_NODES];
__device__ __half g_Xh [(size_t)N_NODES * C1];   // X as fp16
__device__ __half g_X2h[(size_t)N_NODES * C1];   // S*X (fp16, GEMM input)
__device__ __half g_th [(size_t)N_NODES * C1];   // (relu(X2 W1 + s b1)) W2 (fp16)
__device__ __half g_W1T[(size_t)C2 * C1];        // W1^T fp16 [256,128]
__device__ __half g_W2T[(size_t)C1 * C2];        // W2^T fp16 [128,256]
__device__ __half g_Yeh[(size_t)N_HEDGES * C1];  // per-edge aggregate scratch fp16

// ---------------- cp.async helpers ----------------
__device__ __forceinline__ void cp_async16(void* dst, const void* src, bool pred) {
    uint32_t d = (uint32_t)__cvta_generic_to_shared(dst);
    int sz = pred ? 16 : 0;
    asm volatile("cp.async.cg.shared.global [%0], [%1], 16, %2;"
                 :: "r"(d), "l"(src), "r"(sz));
}
#define CP_COMMIT()  asm volatile("cp.async.commit_group;" ::: "memory")
#define CP_WAIT_1()  asm volatile("cp.async.wait_group 1;" ::: "memory")
#define CP_WAIT_0()  asm volatile("cp.async.wait_group 0;" ::: "memory")

// ---------------- setup kernels ----------------
__global__ __launch_bounds__(256)
void zero_counts_kernel() {
    int i = blockIdx.x * 256 + threadIdx.x;
    if (i < N_NODES) { g_dv_cnt[i] = 0; g_cursor[i] = 0; }
}

__global__ __launch_bounds__(256)
void count_kernel(const int* __restrict__ inc_v) {
    int i = blockIdx.x * 256 + threadIdx.x;
    if (i < N_INC) atomicAdd(&g_dv_cnt[inc_v[i]], 1);
}

__global__ __launch_bounds__(256)
void node_scan_phase1() {
    int b = blockIdx.x, t = threadIdx.x;
    int base = b * SCAN_ELEMS + t * 4;
    int s = 0;
    #pragma unroll
    for (int k = 0; k < 4; k++) { int i = base + k; if (i < N_NODES) s += g_dv_cnt[i]; }
    __shared__ int sh[256];
    sh[t] = s; __syncthreads();
    #pragma unroll
    for (int d = 128; d > 0; d >>= 1) { if (t < d) sh[t] += sh[t + d]; __syncthreads(); }
    if (t == 0) g_blk_sums[b] = sh[0];
}

__global__ __launch_bounds__(128)
void node_scan_phase2() {
    int t = threadIdx.x;
    __shared__ int sh[128];
    int v = (t < SCAN_BLOCKS) ? g_blk_sums[t] : 0;
    sh[t] = v; __syncthreads();
    #pragma unroll
    for (int d = 1; d < 128; d <<= 1) {
        int x = (t >= d) ? sh[t - d] : 0; __syncthreads(); sh[t] += x; __syncthreads();
    }
    if (t < SCAN_BLOCKS) g_blk_offs[t] = sh[t] - v;
    if (t == 127) g_node_off[N_NODES] = sh[127];
}

__global__ __launch_bounds__(256)
void node_scan_phase3() {
    int b = blockIdx.x, t = threadIdx.x;
    int base = b * SCAN_ELEMS + t * 4;
    int c[4]; int s = 0;
    #pragma unroll
    for (int k = 0; k < 4; k++) { int i = base + k; c[k] = (i < N_NODES) ? g_dv_cnt[i] : 0; s += c[k]; }
    __shared__ int sh[256];
    sh[t] = s; __syncthreads();
    #pragma unroll
    for (int d = 1; d < 256; d <<= 1) {
        int x = (t >= d) ? sh[t - d] : 0; __syncthreads(); sh[t] += x; __syncthreads();
    }
    int run = g_blk_offs[b] + sh[t] - s;
    #pragma unroll
    for (int k = 0; k < 4; k++) {
        int i = base + k;
        if (i < N_NODES) {
            g_node_off[i] = run; run += c[k];
            g_dvi[i] = (c[k] > 0) ? rsqrtf((float)c[k]) : 0.0f;
        }
    }
}

__global__ __launch_bounds__(256)
void edge_off_kernel(const int* __restrict__ inc_e) {
    int e = blockIdx.x * 256 + threadIdx.x;
    if (e > N_HEDGES) return;
    int lo = 0, hi = N_INC;
    while (lo < hi) { int mid = (lo + hi) >> 1; if (inc_e[mid] < e) lo = mid + 1; else hi = mid; }
    g_edge_off[e] = lo;
}

__global__ __launch_bounds__(256)
void build_csr_kernel(const int* __restrict__ inc_v, const int* __restrict__ inc_e) {
    int i = blockIdx.x * 256 + threadIdx.x;
    if (i < N_INC) {
        int v = inc_v[i];
        int pos = g_node_off[v] + atomicAdd(&g_cursor[v], 1);
        g_node_edges[pos] = inc_e[i];
    }
}

__global__ __launch_bounds__(256)
void te_kernel(const int* __restrict__ inc_v) {
    int e = blockIdx.x * 256 + threadIdx.x;
    if (e >= N_HEDGES) return;
    int b = g_edge_off[e], en = g_edge_off[e + 1];
    float sum = 0.0f;
    for (int i = b; i < en; i++) sum += g_dvi[inc_v[i]];
    float dei = (en > b) ? 1.0f / (float)(en - b) : 0.0f;
    g_te[e] = dei * sum;
}

__global__ __launch_bounds__(256)
void s_kernel() {
    int v = blockIdx.x * 256 + threadIdx.x;
    if (v >= N_NODES) return;
    int b = g_node_off[v], en = g_node_off[v + 1];
    float sum = 0.0f;
    for (int j = b; j < en; j++) sum += g_te[g_node_edges[j]];
    g_s[v] = g_dvi[v] * sum;
}

// weight transpose + fp16: out[n*K + k] = W[k*N + n]
__global__ __launch_bounds__(256)
void wt_kernel(const float* __restrict__ W, __half* __restrict__ out, int K, int N) {
    int i = blockIdx.x * 256 + threadIdx.x;
    if (i < K * N) {
        int n = i / K, k = i % K;
        out[i] = __float2half(W[k * N + n]);
    }
}

// X fp32 -> fp16
__global__ __launch_bounds__(256)
void x_to_h_kernel(const float* __restrict__ X, __half* __restrict__ Xh) {
    int i = blockIdx.x * 256 + threadIdx.x;
    int n = (N_NODES * C1) >> 1;
    if (i < n) {
        float2 v = *(const float2*)(X + i * 2);
        *((__half2*)Xh + i) = __floats2half2_rn(v.x, v.y);
    }
}

// ---------------- gathers ----------------
__device__ __forceinline__ void accum_row_h8(float* a, const __half* __restrict__ row,
                                             int li, float wu) {
    uint4 x = *(const uint4*)(row + li * 8);
    const __half2* hx = (const __half2*)&x;
    float2 f0 = __half22float2(hx[0]);
    float2 f1 = __half22float2(hx[1]);
    float2 f2 = __half22float2(hx[2]);
    float2 f3 = __half22float2(hx[3]);
    a[0] = fmaf(wu, f0.x, a[0]); a[1] = fmaf(wu, f0.y, a[1]);
    a[2] = fmaf(wu, f1.x, a[2]); a[3] = fmaf(wu, f1.y, a[3]);
    a[4] = fmaf(wu, f2.x, a[4]); a[5] = fmaf(wu, f2.y, a[5]);
    a[6] = fmaf(wu, f3.x, a[6]); a[7] = fmaf(wu, f3.y, a[7]);
}

// Ye[e,:] = (1/deg_e) * sum dvi[u] * Xin[u,:]
// use_cnt=1: weight from raw counts (rsqrt), so it can launch before the scan.
__global__ __launch_bounds__(256)
void edge_agg_h_kernel(const __half* __restrict__ Xin, const int* __restrict__ inc_v,
                       int use_cnt) {
    int w = (blockIdx.x * 256 + threadIdx.x) >> 5;
    if (w >= N_HEDGES) return;
    int lane = threadIdx.x & 31;
    int half = lane >> 4, li = lane & 15;
    int b = g_edge_off[w], e = g_edge_off[w + 1];
    float a[8] = {0.f, 0.f, 0.f, 0.f, 0.f, 0.f, 0.f, 0.f};

    int i = b + half;
    if (use_cnt) {
        for (; i + 2 < e; i += 4) {
            int u0 = inc_v[i], u1 = inc_v[i + 2];
            int c0 = g_dv_cnt[u0], c1 = g_dv_cnt[u1];
            float w0 = (c0 > 0) ? rsqrtf((float)c0) : 0.0f;
            float w1 = (c1 > 0) ? rsqrtf((float)c1) : 0.0f;
            accum_row_h8(a, Xin + (size_t)u0 * C1, li, w0);
            accum_row_h8(a, Xin + (size_t)u1 * C1, li, w1);
        }
        if (i < e) {
            int u = inc_v[i];
            int c = g_dv_cnt[u];
            accum_row_h8(a, Xin + (size_t)u * C1, li, (c > 0) ? rsqrtf((float)c) : 0.0f);
        }
    } else {
        for (; i + 2 < e; i += 4) {
            int u0 = inc_v[i], u1 = inc_v[i + 2];
            float w0 = g_dvi[u0], w1 = g_dvi[u1];
            accum_row_h8(a, Xin + (size_t)u0 * C1, li, w0);
            accum_row_h8(a, Xin + (size_t)u1 * C1, li, w1);
        }
        if (i < e) {
            int u = inc_v[i];
            accum_row_h8(a, Xin + (size_t)u * C1, li, g_dvi[u]);
        }
    }
    #pragma unroll
    for (int r = 0; r < 8; r++) a[r] += __shfl_down_sync(0xffffffffu, a[r], 16);
    if (half == 0) {
        float d = (e > b) ? 1.0f / (float)(e - b) : 0.0f;
        uint4 o;
        ((__half2*)&o)[0] = __floats2half2_rn(a[0] * d, a[1] * d);
        ((__half2*)&o)[1] = __floats2half2_rn(a[2] * d, a[3] * d);
        ((__half2*)&o)[2] = __floats2half2_rn(a[4] * d, a[5] * d);
        ((__half2*)&o)[3] = __floats2half2_rn(a[6] * d, a[7] * d);
        *(uint4*)(g_Yeh + (size_t)w * C1 + li * 8) = o;
    }
}

// Xout[v,:] = dvi[v] * sum_e Ye[e,:]
__global__ __launch_bounds__(256)
void node_agg_h_kernel(__half* __restrict__ Xout) {
    int v = (blockIdx.x * 256 + threadIdx.x) >> 5;
    if (v >= N_NODES) return;
    int lane = threadIdx.x & 31;
    int half = lane >> 4, li = lane & 15;
    int b = g_node_off[v], e = g_node_off[v + 1];
    float a[8] = {0.f, 0.f, 0.f, 0.f, 0.f, 0.f, 0.f, 0.f};

    int j = b + half;
    for (; j + 2 < e; j += 4) {
        int e0 = g_node_edges[j], e1 = g_node_edges[j + 2];
        accum_row_h8(a, g_Yeh + (size_t)e0 * C1, li, 1.0f);
        accum_row_h8(a, g_Yeh + (size_t)e1 * C1, li, 1.0f);
    }
    if (j < e) {
        int ee = g_node_edges[j];
        accum_row_h8(a, g_Yeh + (size_t)ee * C1, li, 1.0f);
    }
    #pragma unroll
    for (int r = 0; r < 8; r++) a[r] += __shfl_down_sync(0xffffffffu, a[r], 16);
    if (half == 0) {
        float d = g_dvi[v];
        uint4 o;
        ((__half2*)&o)[0] = __floats2half2_rn(a[0] * d, a[1] * d);
        ((__half2*)&o)[1] = __floats2half2_rn(a[2] * d, a[3] * d);
        ((__half2*)&o)[2] = __floats2half2_rn(a[4] * d, a[5] * d);
        ((__half2*)&o)[3] = __floats2half2_rn(a[6] * d, a[7] * d);
        *(uint4*)(Xout + (size_t)v * C1 + li * 8) = o;
    }
}

// final: zfc[v] = sum_c relu(dvi[v]*agg_c + s[v]*b2[c]) * fcW[c]
__global__ __launch_bounds__(256)
void node_agg_final_kernel(const float* __restrict__ b2, const float* __restrict__ fcW) {
    int v = (blockIdx.x * 256 + threadIdx.x) >> 5;
    if (v >= N_NODES) return;
    int lane = threadIdx.x & 31;
    int half = lane >> 4, li = lane & 15;
    int b = g_node_off[v], e = g_node_off[v + 1];
    float a[8] = {0.f, 0.f, 0.f, 0.f, 0.f, 0.f, 0.f, 0.f};

    int j = b + half;
    for (; j + 2 < e; j += 4) {
        int e0 = g_node_edges[j], e1 = g_node_edges[j + 2];
        accum_row_h8(a, g_Yeh + (size_t)e0 * C1, li, 1.0f);
        accum_row_h8(a, g_Yeh + (size_t)e1 * C1, li, 1.0f);
    }
    if (j < e) {
        int ee = g_node_edges[j];
        accum_row_h8(a, g_Yeh + (size_t)ee * C1, li, 1.0f);
    }
    #pragma unroll
    for (int r = 0; r < 8; r++) a[r] += __shfl_down_sync(0xffffffffu, a[r], 16);

    float p = 0.0f;
    if (half == 0) {
        float d  = g_dvi[v];
        float sv = g_s[v];
        float4 bb0 = *(const float4*)(b2 + li * 8);
        float4 bb1 = *(const float4*)(b2 + li * 8 + 4);
        float4 fw0 = *(const float4*)(fcW + li * 8);
        float4 fw1 = *(const float4*)(fcW + li * 8 + 4);
        p += fmaxf(fmaf(d, a[0], sv * bb0.x), 0.f) * fw0.x;
        p += fmaxf(fmaf(d, a[1], sv * bb0.y), 0.f) * fw0.y;
        p += fmaxf(fmaf(d, a[2], sv * bb0.z), 0.f) * fw0.z;
        p += fmaxf(fmaf(d, a[3], sv * bb0.w), 0.f) * fw0.w;
        p += fmaxf(fmaf(d, a[4], sv * bb1.x), 0.f) * fw1.x;
        p += fmaxf(fmaf(d, a[5], sv * bb1.y), 0.f) * fw1.y;
        p += fmaxf(fmaf(d, a[6], sv * bb1.z), 0.f) * fw1.z;
        p += fmaxf(fmaf(d, a[7], sv * bb1.w), 0.f) * fw1.w;
    }
    #pragma unroll
    for (int o = 8; o > 0; o >>= 1) p += __shfl_down_sync(0xffffffffu, p, o);
    if (lane == 0) g_zfc[v] = p;
}

// ---------------- fused GEMM: t = relu(X2@W1 + s*b1) @ W2 (all weights in smem) ----------------
// smem layout (bytes):
//   [0,        69632)  W1s: [256][136] halves, reused as hs [128][264] after stage 1
//   [69632,   104448)  X2s: [128][136] halves
//   [104448,  172032)  W2s: [128][264] halves
#define FS_X2 69632
#define FS_W2 104448
#define FUSED_SMEM 172032
#define W1S 136
#define X2S 136
#define HS  264
#define W2S 264

__global__ __launch_bounds__(256)
void fused_gemm_kernel(const __half* __restrict__ X2, const __half* __restrict__ W1T,
                       const __half* __restrict__ W2T, int M,
                       const float* __restrict__ s, const float* __restrict__ b1,
                       __half* __restrict__ th) {
    extern __shared__ char sm[];
    __half* W1s = (__half*)sm;             // also hs
    __half* X2s = (__half*)(sm + FS_X2);
    __half* W2s = (__half*)(sm + FS_W2);

    int tid = threadIdx.x;
    int wid = tid >> 5, lane = tid & 31;
    int warp_m = wid >> 2;   // 0..1
    int warp_n = wid & 3;    // 0..3
    int gid = lane >> 2;     // 0..7
    int tig = lane & 3;      // 0..3
    int blockRow = blockIdx.x * 128;

    // --- async loads: group0 = X2 tile + W1, group1 = W2 ---
    #pragma unroll
    for (int t = 0; t < 8; t++) {                 // X2: 128x128 halves = 2048 chunks
        int idx = tid + t * 256;
        int r = idx >> 4, c = (idx & 15) << 3;
        int grow = blockRow + r;
        bool p = grow < M;
        cp_async16(X2s + r * X2S + c, X2 + (size_t)(p ? grow : 0) * C1 + c, p);
    }
    #pragma unroll
    for (int t = 0; t < 16; t++) {                // W1: 256x128 halves = 4096 chunks
        int idx = tid + t * 256;
        int r = idx >> 4, c = (idx & 15) << 3;
        cp_async16(W1s + r * W1S + c, W1T + (size_t)r * C1 + c, true);
    }
    CP_COMMIT();
    #pragma unroll
    for (int t = 0; t < 16; t++) {                // W2: 128x256 halves = 4096 chunks
        int idx = tid + t * 256;
        int r = idx >> 5, c = (idx & 31) << 3;
        cp_async16(W2s + r * W2S + c, W2T + (size_t)r * C2 + c, true);
    }
    CP_COMMIT();
    CP_WAIT_1();     // X2 + W1 ready
    __syncthreads();

    // --- stage 1: h = relu(X2 @ W1T^T + s*b1), two N-halves, kept packed in regs ---
    uint32_t hreg[2][4][4][2];
    #pragma unroll
    for (int nh = 0; nh < 2; nh++) {
        float acc[4][4][4];
        #pragma unroll
        for (int i = 0; i < 4; i++)
            #pragma unroll
            for (int j = 0; j < 4; j++)
                #pragma unroll
                for (int r = 0; r < 4; r++) acc[i][j][r] = 0.f;

        #pragma unroll
        for (int k16 = 0; k16 < C1; k16 += 16) {
            uint32_t af[4][4];
            #pragma unroll
            for (int mt = 0; mt < 4; mt++) {
                int rbase = warp_m * 64 + mt * 16;
                const __half* p0 = X2s + (rbase + gid) * X2S + k16 + tig * 2;
                const __half* p1 = X2s + (rbase + gid + 8) * X2S + k16 + tig * 2;
                af[mt][0] = *(const uint32_t*)p0;
                af[mt][1] = *(const uint32_t*)p1;
                af[mt][2] = *(const uint32_t*)(p0 + 8);
                af[mt][3] = *(const uint32_t*)(p1 + 8);
            }
            uint32_t bf[4][2];
            #pragma unroll
            for (int nt = 0; nt < 4; nt++) {
                int nrow = nh * 128 + warp_n * 32 + nt * 8 + gid;
                const __half* p = W1s + nrow * W1S + k16 + tig * 2;
                bf[nt][0] = *(const uint32_t*)p;
                bf[nt][1] = *(const uint32_t*)(p + 8);
            }
            #pragma unroll
            for (int mt = 0; mt < 4; mt++)
                #pragma unroll
                for (int nt = 0; nt < 4; nt++) {
                    asm volatile(
                        "mma.sync.aligned.m16n8k16.row.col.f32.f16.f16.f32 "
                        "{%0,%1,%2,%3}, {%4,%5,%6,%7}, {%8,%9}, {%0,%1,%2,%3};"
                        : "+f"(acc[mt][nt][0]), "+f"(acc[mt][nt][1]),
                          "+f"(acc[mt][nt][2]), "+f"(acc[mt][nt][3])
                        : "r"(af[mt][0]), "r"(af[mt][1]), "r"(af[mt][2]), "r"(af[mt][3]),
                          "r"(bf[nt][0]), "r"(bf[nt][1]));
                }
        }
        // epilogue -> packed fp16 regs
        #pragma unroll
        for (int mt = 0; mt < 4; mt++) {
            #pragma unroll
            for (int hf = 0; hf < 2; hf++) {
                int row = blockRow + warp_m * 64 + mt * 16 + gid + hf * 8;
                float rs = (row < M) ? s[row] : 0.f;
                #pragma unroll
                for (int nt = 0; nt < 4; nt++) {
                    int col = nh * 128 + warp_n * 32 + nt * 8 + tig * 2;
                    float v0 = fmaxf(fmaf(rs, b1[col],     acc[mt][nt][hf * 2 + 0]), 0.f);
                    float v1 = fmaxf(fmaf(rs, b1[col + 1], acc[mt][nt][hf * 2 + 1]), 0.f);
                    __half2 h2 = __floats2half2_rn(v0, v1);
                    hreg[nh][mt][nt][hf] = *(uint32_t*)&h2;
                }
            }
        }
    }
    __syncthreads();   // all warps done reading W1s

    // --- write h into W1s region (as hs [128][264]) ---
    #pragma unroll
    for (int nh = 0; nh < 2; nh++)
        #pragma unroll
        for (int mt = 0; mt < 4; mt++)
            #pragma unroll
            for (int hf = 0; hf < 2; hf++) {
                int rloc = warp_m * 64 + mt * 16 + gid + hf * 8;
                #pragma unroll
                for (int nt = 0; nt < 4; nt++) {
                    int col = nh * 128 + warp_n * 32 + nt * 8 + tig * 2;
                    *(uint32_t*)(W1s + rloc * HS + col) = hreg[nh][mt][nt][hf];
                }
            }
    CP_WAIT_0();       // W2 ready
    __syncthreads();

    // --- stage 2: t = h @ W2T^T, K=256, all from smem ---
    float acc2[4][4][4];
    #pragma unroll
    for (int i = 0; i < 4; i++)
        #pragma unroll
        for (int j = 0; j < 4; j++)
            #pragma unroll
            for (int r = 0; r < 4; r++) acc2[i][j][r] = 0.f;

    #pragma unroll
    for (int k16 = 0; k16 < C2; k16 += 16) {
        uint32_t af[4][4];
        #pragma unroll
        for (int mt = 0; mt < 4; mt++) {
            int rbase = warp_m * 64 + mt * 16;
            const __half* p0 = W1s + (rbase + gid) * HS + k16 + tig * 2;
            const __half* p1 = W1s + (rbase + gid + 8) * HS + k16 + tig * 2;
            af[mt][0] = *(const uint32_t*)p0;
            af[mt][1] = *(const uint32_t*)p1;
            af[mt][2] = *(const uint32_t*)(p0 + 8);
            af[mt][3] = *(const uint32_t*)(p1 + 8);
        }
        uint32_t bf[4][2];
        #pragma unroll
        for (int nt = 0; nt < 4; nt++) {
            int nrow = warp_n * 32 + nt * 8 + gid;
            const __half* p = W2s + nrow * W2S + k16 + tig * 2;
            bf[nt][0] = *(const uint32_t*)p;
            bf[nt][1] = *(const uint32_t*)(p + 8);
        }
        #pragma unroll
        for (int mt = 0; mt < 4; mt++)
            #pragma unroll
            for (int nt = 0; nt < 4; nt++) {
                asm volatile(
                    "mma.sync.aligned.m16n8k16.row.col.f32.f16.f16.f32 "
                    "{%0,%1,%2,%3}, {%4,%5,%6,%7}, {%8,%9}, {%0,%1,%2,%3};"
                    : "+f"(acc2[mt][nt][0]), "+f"(acc2[mt][nt][1]),
                      "+f"(acc2[mt][nt][2]), "+f"(acc2[mt][nt][3])
                    : "r"(af[mt][0]), "r"(af[mt][1]), "r"(af[mt][2]), "r"(af[mt][3]),
                      "r"(bf[nt][0]), "r"(bf[nt][1]));
            }
    }

    #pragma unroll
    for (int mt = 0; mt < 4; mt++) {
        #pragma unroll
        for (int hf = 0; hf < 2; hf++) {
            int row = blockRow + warp_m * 64 + mt * 16 + gid + hf * 8;
            if (row >= M) continue;
            #pragma unroll
            for (int nt = 0; nt < 4; nt++) {
                int col = warp_n * 32 + nt * 8 + tig * 2;
                *(__half2*)(th + (size_t)row * C1 + col) =
                    __floats2half2_rn(acc2[mt][nt][hf * 2 + 0], acc2[mt][nt][hf * 2 + 1]);
            }
        }
    }
}

// ---------------- link scoring ----------------
__global__ __launch_bounds__(256)
void link_kernel(const int* __restrict__ link, const float* __restrict__ fcb,
                 float* __restrict__ out) {
    int i = blockIdx.x * 256 + threadIdx.x;
    if (i >= N_LINKS) return;
    int a = link[2 * i], b = link[2 * i + 1];
    float x = (g_zfc[a] + g_zfc[b]) * 0.5f + fcb[0];
    out[i] = 1.0f / (1.0f + __expf(-x));
}

// ---------------- launch ----------------
extern "C" void kernel_launch(void* const* d_in, const int* in_sizes, int n_in,
                              void* d_out, int out_size) {
    const float* X    = (const float*)d_in[0];
    const float* W1   = (const float*)d_in[1];
    const float* b1   = (const float*)d_in[2];
    const float* W2   = (const float*)d_in[3];
    const float* b2   = (const float*)d_in[4];
    const float* fcW  = (const float*)d_in[5];
    const float* fcb  = (const float*)d_in[6];
    const int*   incv = (const int*)d_in[7];
    const int*   ince = (const int*)d_in[8];
    const int*   link = (const int*)d_in[9];
    float* out = (float*)d_out;

    static float*  p_s   = nullptr;
    static __half* p_Xh  = nullptr;
    static __half* p_X2h = nullptr;
    static __half* p_th  = nullptr;
    static __half* p_W1T = nullptr;
    static __half* p_W2T = nullptr;
    static cudaStream_t s2 = nullptr, s3 = nullptr;
    static cudaEvent_t evFork = nullptr, evB = nullptr, evCount = nullptr,
                       evC = nullptr, evW2 = nullptr;
    if (!p_s) {
        cudaGetSymbolAddress((void**)&p_s,   g_s);
        cudaGetSymbolAddress((void**)&p_Xh,  g_Xh);
        cudaGetSymbolAddress((void**)&p_X2h, g_X2h);
        cudaGetSymbolAddress((void**)&p_th,  g_th);
        cudaGetSymbolAddress((void**)&p_W1T, g_W1T);
        cudaGetSymbolAddress((void**)&p_W2T, g_W2T);
        cudaStreamCreateWithFlags(&s2, cudaStreamNonBlocking);
        cudaStreamCreateWithFlags(&s3, cudaStreamNonBlocking);
        cudaEventCreateWithFlags(&evFork,  cudaEventDisableTiming);
        cudaEventCreateWithFlags(&evB,     cudaEventDisableTiming);
        cudaEventCreateWithFlags(&evCount, cudaEventDisableTiming);
        cudaEventCreateWithFlags(&evC,     cudaEventDisableTiming);
        cudaEventCreateWithFlags(&evW2,    cudaEventDisableTiming);
        cudaFuncSetAttribute(fused_gemm_kernel,
                             cudaFuncAttributeMaxDynamicSharedMemorySize, FUSED_SMEM);
    }

    const int TPB = 256;
    int inc_blocks    = (N_INC + TPB - 1) / TPB;
    int node_blocks   = (N_NODES + TPB - 1) / TPB;
    int edge_blocks   = (N_HEDGES + 1 + TPB - 1) / TPB;
    int warp_blocks_e = (N_HEDGES * 32 + TPB - 1) / TPB;
    int warp_blocks_n = (N_NODES * 32 + TPB - 1) / TPB;
    int wt_blocks     = (C1 * C2 + TPB - 1) / TPB;
    int xh_blocks     = ((N_NODES * C1 / 2) + TPB - 1) / TPB;
    int gemm_rows     = (N_NODES + 127) / 128;   // 782

    // ---- branch B (s2): inputs for edge_agg1 ----
    cudaEventRecord(evFork, 0);
    cudaStreamWaitEvent(s2, evFork, 0);
    edge_off_kernel<<<edge_blocks, TPB, 0, s2>>>(ince);            // #1
    x_to_h_kernel<<<xh_blocks, TPB, 0, s2>>>(X, p_Xh);             // #2
    wt_kernel<<<wt_blocks, TPB, 0, s2>>>(W1, p_W1T, C1, C2);       // #3
    cudaEventRecord(evB, s2);

    // ---- main: counts, then edge_agg1 immediately ----
    zero_counts_kernel<<<node_blocks, TPB>>>();                    // #4
    count_kernel<<<inc_blocks, TPB>>>(incv);                       // #5
    cudaEventRecord(evCount, 0);
    cudaStreamWaitEvent(0, evB, 0);
    edge_agg_h_kernel<<<warp_blocks_e, TPB>>>(p_Xh, incv, 1);      // #6  (ncu -s 5 target)

    // ---- branch C (s3): scan + csr + te + s, hidden under edge_agg1 ----
    cudaStreamWaitEvent(s3, evCount, 0);
    cudaStreamWaitEvent(s3, evB, 0);
    node_scan_phase1<<<SCAN_BLOCKS, TPB, 0, s3>>>();               // #7
    node_scan_phase2<<<1, 128, 0, s3>>>();                         // #8
    node_scan_phase3<<<SCAN_BLOCKS, TPB, 0, s3>>>();               // #9
    build_csr_kernel<<<inc_blocks, TPB, 0, s3>>>(incv, ince);      // #10
    te_kernel<<<node_blocks, TPB, 0, s3>>>(incv);                  // #11
    s_kernel<<<node_blocks, TPB, 0, s3>>>();                       // #12
    cudaEventRecord(evC, s3);

    // ---- branch B continues: W2 transpose (needed only by fused gemm) ----
    wt_kernel<<<wt_blocks, TPB, 0, s2>>>(W2, p_W2T, C2, C1);       // #13
    cudaEventRecord(evW2, s2);

    // ---- main: node agg, fused GEMM, layer 2, output ----
    cudaStreamWaitEvent(0, evC, 0);
    node_agg_h_kernel<<<warp_blocks_n, TPB>>>(p_X2h);              // #14
    cudaStreamWaitEvent(0, evW2, 0);
    fused_gemm_kernel<<<gemm_rows, 256, FUSED_SMEM>>>(p_X2h, p_W1T, p_W2T,
                                                      N_NODES, p_s, b1, p_th);  // #15
    edge_agg_h_kernel<<<warp_blocks_e, TPB>>>(p_th, incv, 0);      // #16
    node_agg_final_kernel<<<warp_blocks_n, TPB>>>(b2, fcW);        // #17
    link_kernel<<<(N_LINKS + TPB - 1) / TPB, TPB>>>(link, fcb, out); // #18
    (void)in_sizes; (void)n_in; (void)out_size;
}